// round 14
// baseline (speedup 1.0000x reference)
#include <cuda_runtime.h>
#include <cstdint>

// GraphConvolution: y = relu( (D^-1 A) x W^T + b )
// x: [16384, 55, 48] fp32, W: [48,48], b: [48]. A = tridiagonal+self, row-norm.
//
// One block = 6 batch items = 330 rows (tail block: 4 batches / 220 rows).
// 336 threads, 6 output groups x 55 row groups: thread (rg, og) computes
// rows 6*rg..6*rg+5  x  outputs 8*og..8*og+7.
// Scalar-x inner loop (8 LDS.32 per f, bank-free at ROWP=49) + 2 LDS.128 of W
// per f; 24 packed fma.rn.f32x2 per f. Degree scale + bias folded at the end.
// SX_FLOATS padded to a 16-byte boundary so sWt (target of ld.shared.v2.b64)
// is 16B-aligned — R13's misaligned-address trap was exactly this.

#define NB       6
#define NNODES   55
#define NF       48
#define ROWP     49              // odd pitch: conflict-free scalar LDS at 6-row stride
#define THREADS  336
#define ROWSMAX  (NB * NNODES)   // 330
#define NBATCHES 16384

#define SX_RAW      (ROWSMAX * ROWP)               // 16170
#define SX_FLOATS   ((SX_RAW + 3) & ~3)            // 16172 -> sWt 16B-aligned
#define SMEM_FLOATS (SX_FLOATS + NF * NF + NF)     // 18524
#define SMEM_BYTES  (SMEM_FLOATS * 4)              // 74096

__global__ __launch_bounds__(THREADS, 2)
void gconv_o8_kernel(const float* __restrict__ x,
                     const float* __restrict__ W,
                     const float* __restrict__ bias,
                     float* __restrict__ out)
{
    extern __shared__ float smem[];
    float* sx  = smem;                 // [<=330][ROWP], reused for output staging
    float* sWt = smem + SX_FLOATS;     // [NF][NF]  Wt[f][o] = W[o][f], 16B-aligned
    float* sb  = sWt + NF * NF;        // [NF]

    const int t   = threadIdx.x;
    const int bid = blockIdx.x;
    int batches = NBATCHES - bid * NB;
    if (batches > NB) batches = NB;            // tail block has 4
    const int rows_cta = batches * NNODES;
    const int elems4   = rows_cta * (NF / 4);
    const size_t base  = (size_t)bid * (NB * NNODES * NF);

    // ---- stage x (coalesced float4 loads -> scalar STS into pitch-49 rows) ----
    {
        const float4* xg4 = (const float4*)(x + base);
        for (int c = t; c < elems4; c += THREADS) {
            int row = c / (NF / 4), p = c % (NF / 4);
            float4 v = xg4[c];
            float* d = sx + row * ROWP + p * 4;
            d[0] = v.x; d[1] = v.y; d[2] = v.z; d[3] = v.w;
        }
    }
    for (int i = t; i < NF * NF; i += THREADS) {
        int o = i / NF, f = i % NF;
        sWt[f * NF + o] = W[i];
    }
    if (t < NF) sb[t] = bias[t];
    __syncthreads();

    const int og = t % 6;              // outputs 8*og..8*og+7
    const int rg = t / 6;              // rows    6*rg..6*rg+5
    const int r0 = rg * 6;
    const bool active = (r0 < rows_cta);

    unsigned long long acc[6][4];      // [row][output-pair]

    if (active) {
        float wm[6], wp[6];
        #pragma unroll
        for (int i = 0; i < 6; i++) {
            int node = (r0 + i) % NNODES;
            wm[i] = (node > 0)          ? 1.0f : 0.0f;
            wp[i] = (node < NNODES - 1) ? 1.0f : 0.0f;
        }
        // neighbor rows r0-1 .. r0+6 as float offsets (clamped; CTA spans whole
        // batches, so any clamp-overreach lands on a weight-0 lane)
        int offs[8];
        #pragma unroll
        for (int j = 0; j < 8; j++) {
            int rr = r0 - 1 + j;
            rr = rr < 0 ? 0 : (rr > rows_cta - 1 ? rows_cta - 1 : rr);
            offs[j] = rr * ROWP;
        }

        #pragma unroll
        for (int i = 0; i < 6; i++)
            #pragma unroll
            for (int j = 0; j < 4; j++) acc[i][j] = 0ULL;

        const unsigned swt = (unsigned)__cvta_generic_to_shared(sWt) + og * 8 * 4;

        #pragma unroll 2
        for (int f = 0; f < NF; f++) {
            // W for this f: 8 outputs = 4 f32x2 pairs (2 x LDS.128)
            unsigned long long wv[4];
            const unsigned a = swt + f * (NF * 4);
            asm("ld.shared.v2.b64 {%0,%1}, [%2];"
                : "=l"(wv[0]), "=l"(wv[1]) : "r"(a));
            asm("ld.shared.v2.b64 {%0,%1}, [%2];"
                : "=l"(wv[2]), "=l"(wv[3]) : "r"(a + 16));

            // x column f for rows r0-1..r0+6 (scalar, conflict-free)
            float xv[8];
            #pragma unroll
            for (int j = 0; j < 8; j++) xv[j] = sx[offs[j] + f];

            #pragma unroll
            for (int i = 0; i < 6; i++) {
                float av = fmaf(wp[i], xv[i + 2], fmaf(wm[i], xv[i], xv[i + 1]));
                unsigned long long aa;   // {av, av}
                asm("mov.b64 %0, {%1,%1};" : "=l"(aa) : "f"(av));
                #pragma unroll
                for (int j = 0; j < 4; j++)
                    asm("fma.rn.f32x2 %0, %1, %2, %0;"
                        : "+l"(acc[i][j]) : "l"(aa), "l"(wv[j]));
            }
        }

        // ---- fold degree scale + bias: acc = sc*acc + b (packed) ----
        #pragma unroll
        for (int i = 0; i < 6; i++) {
            int node = (r0 + i) % NNODES;
            float sc = (node == 0 || node == NNODES - 1) ? 0.5f : (1.0f / 3.0f);
            unsigned long long ss;
            asm("mov.b64 %0, {%1,%1};" : "=l"(ss) : "f"(sc));
            #pragma unroll
            for (int j = 0; j < 4; j++) {
                float b0 = sb[og * 8 + 2 * j], b1 = sb[og * 8 + 2 * j + 1];
                unsigned long long bb;
                asm("mov.b64 %0, {%1,%2};" : "=l"(bb) : "f"(b0), "f"(b1));
                asm("fma.rn.f32x2 %0, %1, %2, %3;"
                    : "=l"(acc[i][j]) : "l"(acc[i][j]), "l"(ss), "l"(bb));
            }
        }
    }
    __syncthreads();   // all sx reads complete -> safe to reuse as output stage

    // ---- ReLU + stage into sx (scalar STS) ----
    if (active) {
        #pragma unroll
        for (int i = 0; i < 6; i++) {
            if (r0 + i < rows_cta) {
                float* dst = sx + (r0 + i) * ROWP + og * 8;
                #pragma unroll
                for (int j = 0; j < 4; j++) {
                    float a0, a1;
                    asm("mov.b64 {%0,%1}, %2;" : "=f"(a0), "=f"(a1) : "l"(acc[i][j]));
                    dst[2 * j]     = fmaxf(a0, 0.0f);
                    dst[2 * j + 1] = fmaxf(a1, 0.0f);
                }
            }
        }
    }
    __syncthreads();

    // ---- coalesced store (scalar LDS -> float4 STG) ----
    {
        float4* og4 = (float4*)(out + base);
        for (int c = t; c < elems4; c += THREADS) {
            int row = c / (NF / 4), p = c % (NF / 4);
            const float* s = sx + row * ROWP + p * 4;
            og4[c] = make_float4(s[0], s[1], s[2], s[3]);
        }
    }
}

extern "C" void kernel_launch(void* const* d_in, const int* in_sizes, int n_in,
                              void* d_out, int out_size)
{
    const float* x = (const float*)d_in[0];   // [16384, 55, 48]
    const float* W = (const float*)d_in[1];   // [48, 48]
    const float* b = (const float*)d_in[2];   // [48]
    float* out = (float*)d_out;               // [16384, 55, 48]

    (void)in_sizes; (void)n_in; (void)out_size;

    cudaFuncSetAttribute(gconv_o8_kernel,
                         cudaFuncAttributeMaxDynamicSharedMemorySize, SMEM_BYTES);

    const int nblocks = (NBATCHES + NB - 1) / NB;  // 2731 (last block: 4 batches)
    gconv_o8_kernel<<<nblocks, THREADS, SMEM_BYTES>>>(x, W, b, out);
}

// round 15
// speedup vs baseline: 1.0057x; 1.0057x over previous
#include <cuda_runtime.h>
#include <cstdint>

// GraphConvolution: y = relu( (D^-1 A) x W^T + b )
// x: [16384, 55, 48] fp32, W: [48,48], b: [48]. A = tridiagonal+self, row-norm.
//
// One block = 6 batch items = 330 rows (tail block: 4 batches / 220 rows).
// 336 threads, 6 output groups x 55 row groups: thread (rg, og) computes
// rows 6*rg..6*rg+5  x  outputs 8*og..8*og+7.
// Scalar-x inner loop (8 LDS.32 per f, bank-free at ROWP=49) + 2 LDS.128 of W
// per f; 24 packed fma.rn.f32x2 per f. Degree scale + bias folded at the end.
// SX_FLOATS padded to a 16-byte boundary so sWt (target of ld.shared.v2.b64)
// is 16B-aligned — R13's misaligned-address trap was exactly this.

#define NB       6
#define NNODES   55
#define NF       48
#define ROWP     49              // odd pitch: conflict-free scalar LDS at 6-row stride
#define THREADS  336
#define ROWSMAX  (NB * NNODES)   // 330
#define NBATCHES 16384

#define SX_RAW      (ROWSMAX * ROWP)               // 16170
#define SX_FLOATS   ((SX_RAW + 3) & ~3)            // 16172 -> sWt 16B-aligned
#define SMEM_FLOATS (SX_FLOATS + NF * NF + NF)     // 18524
#define SMEM_BYTES  (SMEM_FLOATS * 4)              // 74096

__global__ __launch_bounds__(THREADS, 2)
void gconv_o8_kernel(const float* __restrict__ x,
                     const float* __restrict__ W,
                     const float* __restrict__ bias,
                     float* __restrict__ out)
{
    extern __shared__ float smem[];
    float* sx  = smem;                 // [<=330][ROWP], reused for output staging
    float* sWt = smem + SX_FLOATS;     // [NF][NF]  Wt[f][o] = W[o][f], 16B-aligned
    float* sb  = sWt + NF * NF;        // [NF]

    const int t   = threadIdx.x;
    const int bid = blockIdx.x;
    int batches = NBATCHES - bid * NB;
    if (batches > NB) batches = NB;            // tail block has 4
    const int rows_cta = batches * NNODES;
    const int elems4   = rows_cta * (NF / 4);
    const size_t base  = (size_t)bid * (NB * NNODES * NF);

    // ---- stage x (coalesced float4 loads -> scalar STS into pitch-49 rows) ----
    {
        const float4* xg4 = (const float4*)(x + base);
        for (int c = t; c < elems4; c += THREADS) {
            int row = c / (NF / 4), p = c % (NF / 4);
            float4 v = xg4[c];
            float* d = sx + row * ROWP + p * 4;
            d[0] = v.x; d[1] = v.y; d[2] = v.z; d[3] = v.w;
        }
    }
    for (int i = t; i < NF * NF; i += THREADS) {
        int o = i / NF, f = i % NF;
        sWt[f * NF + o] = W[i];
    }
    if (t < NF) sb[t] = bias[t];
    __syncthreads();

    const int og = t % 6;              // outputs 8*og..8*og+7
    const int rg = t / 6;              // rows    6*rg..6*rg+5
    const int r0 = rg * 6;
    const bool active = (r0 < rows_cta);

    unsigned long long acc[6][4];      // [row][output-pair]

    if (active) {
        float wm[6], wp[6];
        #pragma unroll
        for (int i = 0; i < 6; i++) {
            int node = (r0 + i) % NNODES;
            wm[i] = (node > 0)          ? 1.0f : 0.0f;
            wp[i] = (node < NNODES - 1) ? 1.0f : 0.0f;
        }
        // neighbor rows r0-1 .. r0+6 as float offsets (clamped; CTA spans whole
        // batches, so any clamp-overreach lands on a weight-0 lane)
        int offs[8];
        #pragma unroll
        for (int j = 0; j < 8; j++) {
            int rr = r0 - 1 + j;
            rr = rr < 0 ? 0 : (rr > rows_cta - 1 ? rows_cta - 1 : rr);
            offs[j] = rr * ROWP;
        }

        #pragma unroll
        for (int i = 0; i < 6; i++)
            #pragma unroll
            for (int j = 0; j < 4; j++) acc[i][j] = 0ULL;

        const unsigned swt = (unsigned)__cvta_generic_to_shared(sWt) + og * 8 * 4;

        #pragma unroll 2
        for (int f = 0; f < NF; f++) {
            // W for this f: 8 outputs = 4 f32x2 pairs (2 x LDS.128)
            unsigned long long wv[4];
            const unsigned a = swt + f * (NF * 4);
            asm("ld.shared.v2.b64 {%0,%1}, [%2];"
                : "=l"(wv[0]), "=l"(wv[1]) : "r"(a));
            asm("ld.shared.v2.b64 {%0,%1}, [%2];"
                : "=l"(wv[2]), "=l"(wv[3]) : "r"(a + 16));

            // x column f for rows r0-1..r0+6 (scalar, conflict-free)
            float xv[8];
            #pragma unroll
            for (int j = 0; j < 8; j++) xv[j] = sx[offs[j] + f];

            #pragma unroll
            for (int i = 0; i < 6; i++) {
                float av = fmaf(wp[i], xv[i + 2], fmaf(wm[i], xv[i], xv[i + 1]));
                unsigned long long aa;   // {av, av}
                asm("mov.b64 %0, {%1,%1};" : "=l"(aa) : "f"(av));
                #pragma unroll
                for (int j = 0; j < 4; j++)
                    asm("fma.rn.f32x2 %0, %1, %2, %0;"
                        : "+l"(acc[i][j]) : "l"(aa), "l"(wv[j]));
            }
        }

        // ---- fold degree scale + bias: acc = sc*acc + b (packed) ----
        #pragma unroll
        for (int i = 0; i < 6; i++) {
            int node = (r0 + i) % NNODES;
            float sc = (node == 0 || node == NNODES - 1) ? 0.5f : (1.0f / 3.0f);
            unsigned long long ss;
            asm("mov.b64 %0, {%1,%1};" : "=l"(ss) : "f"(sc));
            #pragma unroll
            for (int j = 0; j < 4; j++) {
                float b0 = sb[og * 8 + 2 * j], b1 = sb[og * 8 + 2 * j + 1];
                unsigned long long bb;
                asm("mov.b64 %0, {%1,%2};" : "=l"(bb) : "f"(b0), "f"(b1));
                asm("fma.rn.f32x2 %0, %1, %2, %3;"
                    : "=l"(acc[i][j]) : "l"(acc[i][j]), "l"(ss), "l"(bb));
            }
        }
    }
    __syncthreads();   // all sx reads complete -> safe to reuse as output stage

    // ---- ReLU + stage into sx (scalar STS) ----
    if (active) {
        #pragma unroll
        for (int i = 0; i < 6; i++) {
            if (r0 + i < rows_cta) {
                float* dst = sx + (r0 + i) * ROWP + og * 8;
                #pragma unroll
                for (int j = 0; j < 4; j++) {
                    float a0, a1;
                    asm("mov.b64 {%0,%1}, %2;" : "=f"(a0), "=f"(a1) : "l"(acc[i][j]));
                    dst[2 * j]     = fmaxf(a0, 0.0f);
                    dst[2 * j + 1] = fmaxf(a1, 0.0f);
                }
            }
        }
    }
    __syncthreads();

    // ---- coalesced store (scalar LDS -> float4 STG) ----
    {
        float4* og4 = (float4*)(out + base);
        for (int c = t; c < elems4; c += THREADS) {
            int row = c / (NF / 4), p = c % (NF / 4);
            const float* s = sx + row * ROWP + p * 4;
            og4[c] = make_float4(s[0], s[1], s[2], s[3]);
        }
    }
}

extern "C" void kernel_launch(void* const* d_in, const int* in_sizes, int n_in,
                              void* d_out, int out_size)
{
    const float* x = (const float*)d_in[0];   // [16384, 55, 48]
    const float* W = (const float*)d_in[1];   // [48, 48]
    const float* b = (const float*)d_in[2];   // [48]
    float* out = (float*)d_out;               // [16384, 55, 48]

    (void)in_sizes; (void)n_in; (void)out_size;

    cudaFuncSetAttribute(gconv_o8_kernel,
                         cudaFuncAttributeMaxDynamicSharedMemorySize, SMEM_BYTES);

    const int nblocks = (NBATCHES + NB - 1) / NB;  // 2731 (last block: 4 batches)
    gconv_o8_kernel<<<nblocks, THREADS, SMEM_BYTES>>>(x, W, b, out);
}